// round 12
// baseline (speedup 1.0000x reference)
#include <cuda_runtime.h>
#include <cuda_bf16.h>
#include <math.h>
#include <stdint.h>

#define SEQ   4096
#define CDIM  128
#define BATCH 4
#define NTOK  (BATCH * SEQ)
#define LN_EPS 1e-5f
#define QSCALE 0.08838834764831845f
#define SOFTMAX_SHIFT 16.0f

// ---- smem word map. Q/K rows stride 68 w, P/V^T rows stride 20 w. ----
#define W_QH   0        // [128][68]
#define W_QL   8704
#define W_KH0  17408    // K buf0 [32][68]
#define W_KL0  19584
#define W_KH1  21760
#define W_KL1  23936
#define W_VH0  26112    // V^T bufs (3x): VH_i = 26112 + i*5120, VL_i = +2560
#define W_PH0  41472    // P bufs (2x): PH_b = 41472 + b*5120, PL_b = +2560
#define W_LRED 51712
#define SMEM_WORDS 51840
#define SMEM_BYTES (SMEM_WORDS * 4)   // 207360
#define W_OS 0          // epilogue: [128][129] f32
#define W_WS 16512      // epilogue: [128][128] f32

// ---------------- global scratch ----------------
__device__ __nv_bfloat16 g_qh[NTOK * CDIM], g_ql[NTOK * CDIM];
__device__ __nv_bfloat16 g_kh[NTOK * CDIM], g_kl[NTOK * CDIM];
__device__ __nv_bfloat16 g_vth[BATCH * CDIM * SEQ], g_vtl[BATCH * CDIM * SEQ];

#define CP_ASYNC16(dst, src) \
    asm volatile("cp.async.cg.shared.global [%0], [%1], 16;" :: "r"(dst), "l"(src))
#define CP_COMMIT() asm volatile("cp.async.commit_group;")
#define CP_WAIT0()  asm volatile("cp.async.wait_group 0;")
#define CP_WAIT1()  asm volatile("cp.async.wait_group 1;")

__device__ __forceinline__ uint32_t smem_addr_u32(const void* p) {
    uint32_t a;
    asm("{ .reg .u64 t; cvta.to.shared.u64 t, %1; cvt.u32.u64 %0, t; }" : "=r"(a) : "l"(p));
    return a;
}
__device__ __forceinline__ uint32_t pack_bf16x2(float a, float b) {
    __nv_bfloat162 h = __floats2bfloat162_rn(a, b);
    return *(uint32_t*)&h;
}
__device__ __forceinline__ void mma16816(float* c, const uint32_t* a, const uint32_t* b) {
    asm volatile(
        "mma.sync.aligned.m16n8k16.row.col.f32.bf16.bf16.f32 "
        "{%0,%1,%2,%3}, {%4,%5,%6,%7}, {%8,%9}, {%0,%1,%2,%3};"
        : "+f"(c[0]), "+f"(c[1]), "+f"(c[2]), "+f"(c[3])
        : "r"(a[0]), "r"(a[1]), "r"(a[2]), "r"(a[3]), "r"(b[0]), "r"(b[1]));
}

// ---------------- fused LayerNorm + QKV (unchanged) ----------------
__global__ __launch_bounds__(256, 1) void ln_qkv_kernel(
    const float* __restrict__ x,
    const float* __restrict__ gamma,
    const float* __restrict__ beta,
    const float* __restrict__ Wq, const float* __restrict__ bq,
    const float* __restrict__ Wk, const float* __restrict__ bk,
    const float* __restrict__ Wv, const float* __restrict__ bv)
{
    __shared__ float xs[64 * 128];
    __shared__ float Wc[64 * 64];

    int tid = threadIdx.x;
    int r0  = blockIdx.x * 64;
    int bbi = r0 >> 12;
    int s0  = r0 & (SEQ - 1);

    {
        int row = tid >> 2, sub = tid & 3;
        const float* xr = x + (size_t)(r0 + row) * CDIM + sub * 32;
        float4 xv[8];
        float s = 0.0f, s2 = 0.0f;
        #pragma unroll
        for (int t = 0; t < 8; t++) {
            xv[t] = *(const float4*)(xr + t * 4);
            s  += xv[t].x + xv[t].y + xv[t].z + xv[t].w;
            s2 += xv[t].x*xv[t].x + xv[t].y*xv[t].y + xv[t].z*xv[t].z + xv[t].w*xv[t].w;
        }
        s  += __shfl_xor_sync(0xffffffffu, s, 1);  s  += __shfl_xor_sync(0xffffffffu, s, 2);
        s2 += __shfl_xor_sync(0xffffffffu, s2, 1); s2 += __shfl_xor_sync(0xffffffffu, s2, 2);
        float mean = s * (1.0f / CDIM);
        float var  = s2 * (1.0f / CDIM) - mean * mean;
        float rstd = rsqrtf(var + LN_EPS);
        #pragma unroll
        for (int t = 0; t < 8; t++) {
            float4 g = *(const float4*)(gamma + sub * 32 + t * 4);
            float4 b = *(const float4*)(beta  + sub * 32 + t * 4);
            float4 o;
            o.x = (xv[t].x - mean) * rstd * g.x + b.x;
            o.y = (xv[t].y - mean) * rstd * g.y + b.y;
            o.z = (xv[t].z - mean) * rstd * g.z + b.z;
            o.w = (xv[t].w - mean) * rstd * g.w + b.w;
            *(float4*)(xs + row * 128 + sub * 32 + t * 4) = o;
        }
    }

    int tx = tid & 15, ty = tid >> 4;
    float vacc[2][4][4];

    #pragma unroll
    for (int w = 0; w < 3; w++) {
        const float* W = (w == 0) ? Wq : (w == 1) ? Wk : Wv;
        const float* bias_ = (w == 0) ? bq : (w == 1) ? bk : bv;
        #pragma unroll
        for (int nch = 0; nch < 2; nch++) {
            float acc[4][4];
            #pragma unroll
            for (int i = 0; i < 4; i++)
                #pragma unroll
                for (int j = 0; j < 4; j++) acc[i][j] = 0.0f;

            #pragma unroll
            for (int kc = 0; kc < 2; kc++) {
                __syncthreads();
                #pragma unroll
                for (int t = 0; t < 4; t++) {
                    int idx = tid + t * 256;
                    int r = idx >> 4, q = idx & 15;
                    *(float4*)(Wc + r * 64 + q * 4) =
                        *(const float4*)(W + (size_t)(kc * 64 + r) * CDIM + nch * 64 + q * 4);
                }
                __syncthreads();
                #pragma unroll 4
                for (int kq = 0; kq < 16; kq++) {
                    float4 b0 = *(const float4*)(Wc + (kq * 4 + 0) * 64 + 4 * tx);
                    float4 b1 = *(const float4*)(Wc + (kq * 4 + 1) * 64 + 4 * tx);
                    float4 b2 = *(const float4*)(Wc + (kq * 4 + 2) * 64 + 4 * tx);
                    float4 b3 = *(const float4*)(Wc + (kq * 4 + 3) * 64 + 4 * tx);
                    #pragma unroll
                    for (int i = 0; i < 4; i++) {
                        float4 a = *(const float4*)(xs + (4 * ty + i) * 128 + kc * 64 + kq * 4);
                        acc[i][0] += a.x * b0.x + a.y * b1.x + a.z * b2.x + a.w * b3.x;
                        acc[i][1] += a.x * b0.y + a.y * b1.y + a.z * b2.y + a.w * b3.y;
                        acc[i][2] += a.x * b0.z + a.y * b1.z + a.z * b2.z + a.w * b3.z;
                        acc[i][3] += a.x * b0.w + a.y * b1.w + a.z * b2.w + a.w * b3.w;
                    }
                }
            }

            float4 bb = *(const float4*)(bias_ + nch * 64 + 4 * tx);
            if (w < 2) {
                float sc = (w == 0) ? QSCALE : 1.0f;
                __nv_bfloat16* dh = (w == 0) ? g_qh : g_kh;
                __nv_bfloat16* dl = (w == 0) ? g_ql : g_kl;
                #pragma unroll
                for (int i = 0; i < 4; i++) {
                    float o0 = (acc[i][0] + bb.x) * sc, o1 = (acc[i][1] + bb.y) * sc;
                    float o2 = (acc[i][2] + bb.z) * sc, o3 = (acc[i][3] + bb.w) * sc;
                    __nv_bfloat16 h0 = __float2bfloat16(o0), h1 = __float2bfloat16(o1);
                    __nv_bfloat16 h2 = __float2bfloat16(o2), h3 = __float2bfloat16(o3);
                    uint2 hv, lv;
                    hv.x = pack_bf16x2(__bfloat162float(h0), __bfloat162float(h1));
                    hv.y = pack_bf16x2(__bfloat162float(h2), __bfloat162float(h3));
                    lv.x = pack_bf16x2(o0 - __bfloat162float(h0), o1 - __bfloat162float(h1));
                    lv.y = pack_bf16x2(o2 - __bfloat162float(h2), o3 - __bfloat162float(h3));
                    size_t e = (size_t)(r0 + 4 * ty + i) * CDIM + nch * 64 + 4 * tx;
                    *(uint2*)(dh + e) = hv;
                    *(uint2*)(dl + e) = lv;
                }
            } else {
                #pragma unroll
                for (int i = 0; i < 4; i++) {
                    vacc[nch][i][0] = acc[i][0] + bb.x;
                    vacc[nch][i][1] = acc[i][1] + bb.y;
                    vacc[nch][i][2] = acc[i][2] + bb.z;
                    vacc[nch][i][3] = acc[i][3] + bb.w;
                }
            }
        }
    }

    __syncthreads();
    #pragma unroll
    for (int nch = 0; nch < 2; nch++)
        #pragma unroll
        for (int i = 0; i < 4; i++)
            *(float4*)(xs + (4 * ty + i) * 128 + nch * 64 + 4 * tx) =
                make_float4(vacc[nch][i][0], vacc[nch][i][1], vacc[nch][i][2], vacc[nch][i][3]);
    __syncthreads();

    {
        int ch = tid >> 1, sh = tid & 1;
        size_t base = ((size_t)(bbi * CDIM + ch)) * SEQ + s0 + sh * 32;
        #pragma unroll
        for (int g = 0; g < 8; g++) {
            float v0 = xs[(sh * 32 + g * 4 + 0) * 128 + ch];
            float v1 = xs[(sh * 32 + g * 4 + 1) * 128 + ch];
            float v2 = xs[(sh * 32 + g * 4 + 2) * 128 + ch];
            float v3 = xs[(sh * 32 + g * 4 + 3) * 128 + ch];
            __nv_bfloat16 h0 = __float2bfloat16(v0), h1 = __float2bfloat16(v1);
            __nv_bfloat16 h2 = __float2bfloat16(v2), h3 = __float2bfloat16(v3);
            uint2 hv, lv;
            hv.x = pack_bf16x2(__bfloat162float(h0), __bfloat162float(h1));
            hv.y = pack_bf16x2(__bfloat162float(h2), __bfloat162float(h3));
            lv.x = pack_bf16x2(v0 - __bfloat162float(h0), v1 - __bfloat162float(h1));
            lv.y = pack_bf16x2(v2 - __bfloat162float(h2), v3 - __bfloat162float(h3));
            *(uint2*)(g_vth + base + g * 4) = hv;
            *(uint2*)(g_vtl + base + g * 4) = lv;
        }
    }
}

// ---------------- pipelined HMMA flash attention, 512 threads (16 warps) --------
// Warp w: S tile rows 16*(w>>1) x keys 16*(w&1); PV tile rows 16*(w>>1) x chans 64*(w&1).

__device__ __forceinline__ void load_K_tile(uint32_t sb, int tid, int khw, int klw,
                                            size_t krow0) {
    #pragma unroll
    for (int j = 0; j < 2; j++) {
        int id = tid + j * 512;
        int hi = id < 512;
        int c = id & 511;
        int row = c >> 4, ch8 = c & 15;
        uint32_t dst = sb + (uint32_t)(((hi ? khw : klw) + row * 68 + ch8 * 4) * 4);
        const __nv_bfloat16* src = (hi ? g_kh : g_kl) + (krow0 + row) * CDIM + ch8 * 8;
        CP_ASYNC16(dst, src);
    }
}
__device__ __forceinline__ void load_V_tile(uint32_t sb, int tid, int vhw, int vlw,
                                            size_t vch0, int skey) {
    #pragma unroll
    for (int j = 0; j < 2; j++) {
        int id = tid + j * 512;
        int hi = id < 512;
        int c = id & 511;
        int ch = c >> 2, k8 = c & 3;
        uint32_t dst = sb + (uint32_t)(((hi ? vhw : vlw) + ch * 20 + k8 * 4) * 4);
        const __nv_bfloat16* src = (hi ? g_vth : g_vtl) + (vch0 + ch) * SEQ + skey + k8 * 8;
        CP_ASYNC16(dst, src);
    }
}

__device__ __forceinline__ void compute_S(const uint32_t* sm32, int khw, int klw,
        int mrow0, int sk0, int lr, int lc, float sacc[2][4]) {
    const uint32_t* Kh32 = sm32 + khw;
    const uint32_t* Kl32 = sm32 + klw;
    #pragma unroll
    for (int nt = 0; nt < 2; nt++)
        #pragma unroll
        for (int r = 0; r < 4; r++) sacc[nt][r] = 0.0f;
    #pragma unroll
    for (int kt = 0; kt < 8; kt++) {
        uint32_t bh[2][2], bl[2][2];
        #pragma unroll
        for (int nt = 0; nt < 2; nt++) {
            int bbase = (sk0 + nt * 8 + lr) * 68 + kt * 8 + lc;
            bh[nt][0] = Kh32[bbase]; bh[nt][1] = Kh32[bbase + 4];
            bl[nt][0] = Kl32[bbase]; bl[nt][1] = Kl32[bbase + 4];
        }
        int ab = (mrow0 + lr) * 68 + kt * 8 + lc;
        uint32_t ah[4], al[4];
        ah[0] = sm32[W_QH + ab];       ah[1] = sm32[W_QH + ab + 544];
        ah[2] = sm32[W_QH + ab + 4];   ah[3] = sm32[W_QH + ab + 548];
        al[0] = sm32[W_QL + ab];       al[1] = sm32[W_QL + ab + 544];
        al[2] = sm32[W_QL + ab + 4];   al[3] = sm32[W_QL + ab + 548];
        #pragma unroll
        for (int nt = 0; nt < 2; nt++) {
            mma16816(sacc[nt], ah, bh[nt]);
            mma16816(sacc[nt], ah, bl[nt]);
            mma16816(sacc[nt], al, bh[nt]);
        }
    }
}

__device__ __forceinline__ void softmax_store(uint32_t* sm32, float sacc[2][4],
        int phw, int plw, int mrow0, int sk0, int lr, int lc, float* lpart) {
    #pragma unroll
    for (int nt = 0; nt < 2; nt++) {
        float* c = sacc[nt];
        float p0 = __expf(c[0] - SOFTMAX_SHIFT);
        float p1 = __expf(c[1] - SOFTMAX_SHIFT);
        float p2 = __expf(c[2] - SOFTMAX_SHIFT);
        float p3 = __expf(c[3] - SOFTMAX_SHIFT);
        lpart[0] += p0 + p1;
        lpart[1] += p2 + p3;
        __nv_bfloat16 h0 = __float2bfloat16(p0), h1 = __float2bfloat16(p1);
        __nv_bfloat16 h2 = __float2bfloat16(p2), h3 = __float2bfloat16(p3);
        int r0w = (mrow0 + lr) * 20 + sk0 / 2 + nt * 4 + lc;
        int r1w = r0w + 160;   // +8 rows * 20
        sm32[phw + r0w] = pack_bf16x2(__bfloat162float(h0), __bfloat162float(h1));
        sm32[plw + r0w] = pack_bf16x2(p0 - __bfloat162float(h0), p1 - __bfloat162float(h1));
        sm32[phw + r1w] = pack_bf16x2(__bfloat162float(h2), __bfloat162float(h3));
        sm32[plw + r1w] = pack_bf16x2(p2 - __bfloat162float(h2), p3 - __bfloat162float(h3));
    }
}

__device__ __forceinline__ void compute_PV(const uint32_t* sm32, int phw, int plw,
        int vhw, int vlw, int mrow0, int oc0, int lr, int lc, float (*oacc)[4]) {
    const uint32_t* Vh32 = sm32 + vhw;
    const uint32_t* Vl32 = sm32 + vlw;
    #pragma unroll
    for (int kt = 0; kt < 2; kt++) {
        uint32_t aph[4], apl[4];
        int pb = (mrow0 + lr) * 20 + kt * 8 + lc;
        aph[0] = sm32[phw + pb];       aph[1] = sm32[phw + pb + 160];
        aph[2] = sm32[phw + pb + 4];   aph[3] = sm32[phw + pb + 164];
        apl[0] = sm32[plw + pb];       apl[1] = sm32[plw + pb + 160];
        apl[2] = sm32[plw + pb + 4];   apl[3] = sm32[plw + pb + 164];
        #pragma unroll
        for (int nt = 0; nt < 8; nt++) {
            int vb = (oc0 + nt * 8 + lr) * 20 + kt * 8 + lc;
            uint32_t bvh[2], bvl[2];
            bvh[0] = Vh32[vb]; bvh[1] = Vh32[vb + 4];
            bvl[0] = Vl32[vb]; bvl[1] = Vl32[vb + 4];
            mma16816(oacc[nt], aph, bvh);
            mma16816(oacc[nt], aph, bvl);
            mma16816(oacc[nt], apl, bvh);
        }
    }
}

__global__ __launch_bounds__(512, 1) void attn_kernel(
    const float* __restrict__ Wo,
    const float* __restrict__ bo,
    float* __restrict__ outdst)
{
    extern __shared__ uint32_t sm32[];
    float* smf = (float*)sm32;
    uint32_t sb = smem_addr_u32(sm32);

    int tid = threadIdx.x, wid = tid >> 5, lane = tid & 31;
    int lr = lane >> 2, lc = lane & 3;
    int qt = blockIdx.x, bbx = blockIdx.y;
    size_t qrow0 = (size_t)bbx * SEQ + (size_t)qt * 128;
    size_t krow0 = (size_t)bbx * SEQ;
    size_t vch0  = (size_t)bbx * CDIM;

    int mrow0 = (wid >> 1) * 16;
    int sk0   = (wid & 1) * 16;
    int oc0   = (wid & 1) * 64;

    if (tid < 128) smf[W_LRED + tid] = 0.0f;

    // Q (hi+lo) via cp.async: 4096 chunks, 8 per thread
    #pragma unroll
    for (int j = 0; j < 8; j++) {
        int id = tid + j * 512;
        int hi = id < 2048;
        int c = id & 2047;
        int row = c >> 4, ch8 = c & 15;
        uint32_t dst = sb + (uint32_t)(((hi ? W_QH : W_QL) + row * 68 + ch8 * 4) * 4);
        const __nv_bfloat16* src = (hi ? g_qh : g_ql) + (qrow0 + row) * CDIM + ch8 * 8;
        CP_ASYNC16(dst, src);
    }
    load_K_tile(sb, tid, W_KH0, W_KL0, krow0);
    load_V_tile(sb, tid, W_VH0, W_VH0 + 2560, vch0, 0);
    CP_COMMIT();
    load_K_tile(sb, tid, W_KH1, W_KL1, krow0 + 32);
    load_V_tile(sb, tid, W_VH0 + 5120, W_VH0 + 7680, vch0, 32);
    CP_COMMIT();

    float oacc[8][4];
    #pragma unroll
    for (int nt = 0; nt < 8; nt++)
        #pragma unroll
        for (int r = 0; r < 4; r++) oacc[nt][r] = 0.0f;
    float lpart[2] = {0.0f, 0.0f};
    float sacc[2][4];

    // prologue: S(0) + P(0)
    CP_WAIT1();
    __syncthreads();
    compute_S(sm32, W_KH0, W_KL0, mrow0, sk0, lr, lc, sacc);
    softmax_store(sm32, sacc, W_PH0, W_PH0 + 2560, mrow0, sk0, lr, lc, lpart);

    int vcur = 0;
    for (int t = 0; t < SEQ / 32; t++) {
        if (t < 127) CP_WAIT0();
        __syncthreads();

        if (t < 126) {
            int vpf = vcur - 1; if (vpf < 0) vpf += 3;
            load_K_tile(sb, tid, (t & 1) ? W_KH1 : W_KH0, (t & 1) ? W_KL1 : W_KL0,
                        krow0 + (size_t)(t + 2) * 32);
            load_V_tile(sb, tid, W_VH0 + vpf * 5120, W_VH0 + vpf * 5120 + 2560,
                        vch0, (t + 2) * 32);
            CP_COMMIT();
        }

        if (t < 127)
            compute_S(sm32, ((t + 1) & 1) ? W_KH1 : W_KH0,
                      ((t + 1) & 1) ? W_KL1 : W_KL0, mrow0, sk0, lr, lc, sacc);

        {
            int phw = W_PH0 + (t & 1) * 5120;
            int vhw = W_VH0 + vcur * 5120;
            compute_PV(sm32, phw, phw + 2560, vhw, vhw + 2560, mrow0, oc0, lr, lc, oacc);
        }

        if (t < 127) {
            int phw = W_PH0 + ((t + 1) & 1) * 5120;
            softmax_store(sm32, sacc, phw, phw + 2560, mrow0, sk0, lr, lc, lpart);
        }

        vcur = (vcur == 2) ? 0 : vcur + 1;
    }

    // ---- l reduction ----
    __syncthreads();
    atomicAdd(&smf[W_LRED + mrow0 + lr], lpart[0]);
    atomicAdd(&smf[W_LRED + mrow0 + 8 + lr], lpart[1]);
    __syncthreads();
    float rl0 = 1.0f / smf[W_LRED + mrow0 + lr];
    float rl1 = 1.0f / smf[W_LRED + mrow0 + 8 + lr];
    __syncthreads();

    // ---- write normalized O; load Wo ----
    #pragma unroll
    for (int nt = 0; nt < 8; nt++) {
        int ch = oc0 + nt * 8 + 2 * lc;
        int ra = mrow0 + lr;
        smf[W_OS + ra * 129 + ch]           = oacc[nt][0] * rl0;
        smf[W_OS + ra * 129 + ch + 1]       = oacc[nt][1] * rl0;
        smf[W_OS + (ra + 8) * 129 + ch]     = oacc[nt][2] * rl1;
        smf[W_OS + (ra + 8) * 129 + ch + 1] = oacc[nt][3] * rl1;
    }
    #pragma unroll
    for (int j = 0; j < 8; j++) {
        int idx = tid + j * 512;
        int rr = idx >> 5, cc = idx & 31;
        *(float4*)(smf + W_WS + rr * 128 + cc * 4) = *(const float4*)(Wo + (size_t)rr * 128 + cc * 4);
    }
    __syncthreads();

    // ---- out-proj: thread = (row, quarter) -> 32 cols ----
    {
        int row = tid >> 2, qd = tid & 3;
        float facc[32];
        #pragma unroll
        for (int j = 0; j < 32; j++) facc[j] = 0.0f;
        #pragma unroll 4
        for (int k = 0; k < 128; k++) {
            float o = smf[W_OS + row * 129 + k];
            #pragma unroll
            for (int c4 = 0; c4 < 8; c4++) {
                float4 w = *(const float4*)(smf + W_WS + k * 128 + qd * 32 + c4 * 4);
                facc[c4 * 4 + 0] += o * w.x;
                facc[c4 * 4 + 1] += o * w.y;
                facc[c4 * 4 + 2] += o * w.z;
                facc[c4 * 4 + 3] += o * w.w;
            }
        }
        #pragma unroll
        for (int c4 = 0; c4 < 8; c4++) {
            float4 bb = *(const float4*)(bo + qd * 32 + c4 * 4);
            float4 f;
            f.x = facc[c4 * 4 + 0] + bb.x;
            f.y = facc[c4 * 4 + 1] + bb.y;
            f.z = facc[c4 * 4 + 2] + bb.z;
            f.w = facc[c4 * 4 + 3] + bb.w;
            *(float4*)(outdst + (qrow0 + row) * CDIM + qd * 32 + c4 * 4) = f;
        }
    }
}

// ---------------- eager module load ----------------
namespace {
struct CudaPrewarm {
    CudaPrewarm() {
        cudaFuncAttributes a;
        cudaFuncGetAttributes(&a, (const void*)ln_qkv_kernel);
        cudaFuncGetAttributes(&a, (const void*)attn_kernel);
        cudaFuncSetAttribute(attn_kernel, cudaFuncAttributeMaxDynamicSharedMemorySize, SMEM_BYTES);
    }
};
CudaPrewarm g_prewarm;
}

// ---------------- launch ----------------
extern "C" void kernel_launch(void* const* d_in, const int* in_sizes, int n_in,
                              void* d_out, int out_size)
{
    const float* x     = (const float*)d_in[0];
    const float* gamma = (const float*)d_in[1];
    const float* beta  = (const float*)d_in[2];
    const float* Wq    = (const float*)d_in[3];
    const float* bq    = (const float*)d_in[4];
    const float* Wk    = (const float*)d_in[5];
    const float* bk    = (const float*)d_in[6];
    const float* Wv    = (const float*)d_in[7];
    const float* bv    = (const float*)d_in[8];
    const float* Wo    = (const float*)d_in[9];
    const float* bo    = (const float*)d_in[10];
    float* out = (float*)d_out;

    cudaFuncSetAttribute(attn_kernel, cudaFuncAttributeMaxDynamicSharedMemorySize, SMEM_BYTES);

    ln_qkv_kernel<<<NTOK / 64, 256>>>(x, gamma, beta, Wq, bq, Wk, bk, Wv, bv);
    attn_kernel<<<dim3(SEQ / 128, BATCH), 512, SMEM_BYTES>>>(Wo, bo, out);
}

// round 13
// speedup vs baseline: 1.5446x; 1.5446x over previous
#include <cuda_runtime.h>
#include <cuda_bf16.h>
#include <math.h>
#include <stdint.h>

#define SEQ   4096
#define CDIM  128
#define BATCH 4
#define NTOK  (BATCH * SEQ)
#define LN_EPS 1e-5f
#define QSCALE 0.08838834764831845f
#define SOFTMAX_SHIFT 16.0f

// ---- smem word map. Q/K rows stride 68 w, P/V^T rows stride 20 w. ----
#define W_QH   0        // [128][68]
#define W_QL   8704
#define W_KH0  17408    // K buf0 [32][68]
#define W_KL0  19584
#define W_KH1  21760
#define W_KL1  23936
#define W_VH0  26112    // V^T bufs (3x): VH_i = 26112 + i*5120, VL_i = +2560
#define W_PH0  41472    // P bufs (2x, hi only used): PH_b = 41472 + b*5120
#define W_LRED 51712
#define SMEM_WORDS 51840
#define SMEM_BYTES (SMEM_WORDS * 4)   // 207360
#define W_OS 0          // epilogue: [128][129] f32
#define W_WS 16512      // epilogue: [128][128] f32

// ---------------- global scratch ----------------
__device__ __nv_bfloat16 g_qh[NTOK * CDIM], g_ql[NTOK * CDIM];
__device__ __nv_bfloat16 g_kh[NTOK * CDIM], g_kl[NTOK * CDIM];
__device__ __nv_bfloat16 g_vth[BATCH * CDIM * SEQ], g_vtl[BATCH * CDIM * SEQ];

#define CP_ASYNC16(dst, src) \
    asm volatile("cp.async.cg.shared.global [%0], [%1], 16;" :: "r"(dst), "l"(src))
#define CP_COMMIT() asm volatile("cp.async.commit_group;")
#define CP_WAIT0()  asm volatile("cp.async.wait_group 0;")
#define CP_WAIT1()  asm volatile("cp.async.wait_group 1;")

#define LDSM_X4(r0, r1, r2, r3, addr) \
    asm volatile("ldmatrix.sync.aligned.m8n8.x4.shared.b16 {%0,%1,%2,%3}, [%4];" \
        : "=r"(r0), "=r"(r1), "=r"(r2), "=r"(r3) : "r"(addr))

__device__ __forceinline__ uint32_t smem_addr_u32(const void* p) {
    uint32_t a;
    asm("{ .reg .u64 t; cvta.to.shared.u64 t, %1; cvt.u32.u64 %0, t; }" : "=r"(a) : "l"(p));
    return a;
}
__device__ __forceinline__ uint32_t pack_bf16x2(float a, float b) {
    __nv_bfloat162 h = __floats2bfloat162_rn(a, b);
    return *(uint32_t*)&h;
}
__device__ __forceinline__ void mma16816(float* c, const uint32_t* a, const uint32_t* b) {
    asm volatile(
        "mma.sync.aligned.m16n8k16.row.col.f32.bf16.bf16.f32 "
        "{%0,%1,%2,%3}, {%4,%5,%6,%7}, {%8,%9}, {%0,%1,%2,%3};"
        : "+f"(c[0]), "+f"(c[1]), "+f"(c[2]), "+f"(c[3])
        : "r"(a[0]), "r"(a[1]), "r"(a[2]), "r"(a[3]), "r"(b[0]), "r"(b[1]));
}

// ---------------- fused LayerNorm + QKV (unchanged) ----------------
__global__ __launch_bounds__(256, 1) void ln_qkv_kernel(
    const float* __restrict__ x,
    const float* __restrict__ gamma,
    const float* __restrict__ beta,
    const float* __restrict__ Wq, const float* __restrict__ bq,
    const float* __restrict__ Wk, const float* __restrict__ bk,
    const float* __restrict__ Wv, const float* __restrict__ bv)
{
    __shared__ float xs[64 * 128];
    __shared__ float Wc[64 * 64];

    int tid = threadIdx.x;
    int r0  = blockIdx.x * 64;
    int bbi = r0 >> 12;
    int s0  = r0 & (SEQ - 1);

    {
        int row = tid >> 2, sub = tid & 3;
        const float* xr = x + (size_t)(r0 + row) * CDIM + sub * 32;
        float4 xv[8];
        float s = 0.0f, s2 = 0.0f;
        #pragma unroll
        for (int t = 0; t < 8; t++) {
            xv[t] = *(const float4*)(xr + t * 4);
            s  += xv[t].x + xv[t].y + xv[t].z + xv[t].w;
            s2 += xv[t].x*xv[t].x + xv[t].y*xv[t].y + xv[t].z*xv[t].z + xv[t].w*xv[t].w;
        }
        s  += __shfl_xor_sync(0xffffffffu, s, 1);  s  += __shfl_xor_sync(0xffffffffu, s, 2);
        s2 += __shfl_xor_sync(0xffffffffu, s2, 1); s2 += __shfl_xor_sync(0xffffffffu, s2, 2);
        float mean = s * (1.0f / CDIM);
        float var  = s2 * (1.0f / CDIM) - mean * mean;
        float rstd = rsqrtf(var + LN_EPS);
        #pragma unroll
        for (int t = 0; t < 8; t++) {
            float4 g = *(const float4*)(gamma + sub * 32 + t * 4);
            float4 b = *(const float4*)(beta  + sub * 32 + t * 4);
            float4 o;
            o.x = (xv[t].x - mean) * rstd * g.x + b.x;
            o.y = (xv[t].y - mean) * rstd * g.y + b.y;
            o.z = (xv[t].z - mean) * rstd * g.z + b.z;
            o.w = (xv[t].w - mean) * rstd * g.w + b.w;
            *(float4*)(xs + row * 128 + sub * 32 + t * 4) = o;
        }
    }

    int tx = tid & 15, ty = tid >> 4;
    float vacc[2][4][4];

    #pragma unroll
    for (int w = 0; w < 3; w++) {
        const float* W = (w == 0) ? Wq : (w == 1) ? Wk : Wv;
        const float* bias_ = (w == 0) ? bq : (w == 1) ? bk : bv;
        #pragma unroll
        for (int nch = 0; nch < 2; nch++) {
            float acc[4][4];
            #pragma unroll
            for (int i = 0; i < 4; i++)
                #pragma unroll
                for (int j = 0; j < 4; j++) acc[i][j] = 0.0f;

            #pragma unroll
            for (int kc = 0; kc < 2; kc++) {
                __syncthreads();
                #pragma unroll
                for (int t = 0; t < 4; t++) {
                    int idx = tid + t * 256;
                    int r = idx >> 4, q = idx & 15;
                    *(float4*)(Wc + r * 64 + q * 4) =
                        *(const float4*)(W + (size_t)(kc * 64 + r) * CDIM + nch * 64 + q * 4);
                }
                __syncthreads();
                #pragma unroll 4
                for (int kq = 0; kq < 16; kq++) {
                    float4 b0 = *(const float4*)(Wc + (kq * 4 + 0) * 64 + 4 * tx);
                    float4 b1 = *(const float4*)(Wc + (kq * 4 + 1) * 64 + 4 * tx);
                    float4 b2 = *(const float4*)(Wc + (kq * 4 + 2) * 64 + 4 * tx);
                    float4 b3 = *(const float4*)(Wc + (kq * 4 + 3) * 64 + 4 * tx);
                    #pragma unroll
                    for (int i = 0; i < 4; i++) {
                        float4 a = *(const float4*)(xs + (4 * ty + i) * 128 + kc * 64 + kq * 4);
                        acc[i][0] += a.x * b0.x + a.y * b1.x + a.z * b2.x + a.w * b3.x;
                        acc[i][1] += a.x * b0.y + a.y * b1.y + a.z * b2.y + a.w * b3.y;
                        acc[i][2] += a.x * b0.z + a.y * b1.z + a.z * b2.z + a.w * b3.z;
                        acc[i][3] += a.x * b0.w + a.y * b1.w + a.z * b2.w + a.w * b3.w;
                    }
                }
            }

            float4 bb = *(const float4*)(bias_ + nch * 64 + 4 * tx);
            if (w < 2) {
                float sc = (w == 0) ? QSCALE : 1.0f;
                __nv_bfloat16* dh = (w == 0) ? g_qh : g_kh;
                __nv_bfloat16* dl = (w == 0) ? g_ql : g_kl;
                #pragma unroll
                for (int i = 0; i < 4; i++) {
                    float o0 = (acc[i][0] + bb.x) * sc, o1 = (acc[i][1] + bb.y) * sc;
                    float o2 = (acc[i][2] + bb.z) * sc, o3 = (acc[i][3] + bb.w) * sc;
                    __nv_bfloat16 h0 = __float2bfloat16(o0), h1 = __float2bfloat16(o1);
                    __nv_bfloat16 h2 = __float2bfloat16(o2), h3 = __float2bfloat16(o3);
                    uint2 hv, lv;
                    hv.x = pack_bf16x2(__bfloat162float(h0), __bfloat162float(h1));
                    hv.y = pack_bf16x2(__bfloat162float(h2), __bfloat162float(h3));
                    lv.x = pack_bf16x2(o0 - __bfloat162float(h0), o1 - __bfloat162float(h1));
                    lv.y = pack_bf16x2(o2 - __bfloat162float(h2), o3 - __bfloat162float(h3));
                    size_t e = (size_t)(r0 + 4 * ty + i) * CDIM + nch * 64 + 4 * tx;
                    *(uint2*)(dh + e) = hv;
                    *(uint2*)(dl + e) = lv;
                }
            } else {
                #pragma unroll
                for (int i = 0; i < 4; i++) {
                    vacc[nch][i][0] = acc[i][0] + bb.x;
                    vacc[nch][i][1] = acc[i][1] + bb.y;
                    vacc[nch][i][2] = acc[i][2] + bb.z;
                    vacc[nch][i][3] = acc[i][3] + bb.w;
                }
            }
        }
    }

    __syncthreads();
    #pragma unroll
    for (int nch = 0; nch < 2; nch++)
        #pragma unroll
        for (int i = 0; i < 4; i++)
            *(float4*)(xs + (4 * ty + i) * 128 + nch * 64 + 4 * tx) =
                make_float4(vacc[nch][i][0], vacc[nch][i][1], vacc[nch][i][2], vacc[nch][i][3]);
    __syncthreads();

    {
        int ch = tid >> 1, sh = tid & 1;
        size_t base = ((size_t)(bbi * CDIM + ch)) * SEQ + s0 + sh * 32;
        #pragma unroll
        for (int g = 0; g < 8; g++) {
            float v0 = xs[(sh * 32 + g * 4 + 0) * 128 + ch];
            float v1 = xs[(sh * 32 + g * 4 + 1) * 128 + ch];
            float v2 = xs[(sh * 32 + g * 4 + 2) * 128 + ch];
            float v3 = xs[(sh * 32 + g * 4 + 3) * 128 + ch];
            __nv_bfloat16 h0 = __float2bfloat16(v0), h1 = __float2bfloat16(v1);
            __nv_bfloat16 h2 = __float2bfloat16(v2), h3 = __float2bfloat16(v3);
            uint2 hv, lv;
            hv.x = pack_bf16x2(__bfloat162float(h0), __bfloat162float(h1));
            hv.y = pack_bf16x2(__bfloat162float(h2), __bfloat162float(h3));
            lv.x = pack_bf16x2(v0 - __bfloat162float(h0), v1 - __bfloat162float(h1));
            lv.y = pack_bf16x2(v2 - __bfloat162float(h2), v3 - __bfloat162float(h3));
            *(uint2*)(g_vth + base + g * 4) = hv;
            *(uint2*)(g_vtl + base + g * 4) = lv;
        }
    }
}

// ---------------- pipelined HMMA flash attention, 8 warps, ldmatrix -----------
// Warp w: S rows 32*(w>>1) x keys 16*(w&1); PV rows 32*(w>>1) x chans 64*(w&1).

__device__ __forceinline__ void load_K_tile(uint32_t sb, int tid, int khw, int klw,
                                            size_t krow0) {
    #pragma unroll
    for (int j = 0; j < 4; j++) {
        int id = tid + j * 256;
        int hi = id < 512;
        int c = id & 511;
        int row = c >> 4, ch8 = c & 15;
        uint32_t dst = sb + (uint32_t)(((hi ? khw : klw) + row * 68 + ch8 * 4) * 4);
        const __nv_bfloat16* src = (hi ? g_kh : g_kl) + (krow0 + row) * CDIM + ch8 * 8;
        CP_ASYNC16(dst, src);
    }
}
__device__ __forceinline__ void load_V_tile(uint32_t sb, int tid, int vhw, int vlw,
                                            size_t vch0, int skey) {
    #pragma unroll
    for (int j = 0; j < 4; j++) {
        int id = tid + j * 256;
        int hi = id < 512;
        int c = id & 511;
        int ch = c >> 2, k8 = c & 3;
        uint32_t dst = sb + (uint32_t)(((hi ? vhw : vlw) + ch * 20 + k8 * 4) * 4);
        const __nv_bfloat16* src = (hi ? g_vth : g_vtl) + (vch0 + ch) * SEQ + skey + k8 * 8;
        CP_ASYNC16(dst, src);
    }
}

// S = Q@K^T (3-term split); ldmatrix fragments.
__device__ __forceinline__ void compute_S(uint32_t sb, int khw, int klw,
        int mrow0, int sk0, int lane, float sacc[2][2][4]) {
    uint32_t q_l = (uint32_t)((mrow0 + (lane & 15)) * 68 + (lane >> 4) * 4);
    uint32_t k_l = (uint32_t)((sk0 + ((lane >> 4) << 3) + (lane & 7)) * 68 + ((lane >> 3) & 1) * 4);
    #pragma unroll
    for (int mt = 0; mt < 2; mt++)
        #pragma unroll
        for (int nt = 0; nt < 2; nt++)
            #pragma unroll
            for (int r = 0; r < 4; r++) sacc[mt][nt][r] = 0.0f;
    #pragma unroll
    for (int kt = 0; kt < 8; kt++) {
        uint32_t bh[4], bl[4];
        LDSM_X4(bh[0], bh[1], bh[2], bh[3], sb + 4u * (khw + k_l + kt * 8));
        LDSM_X4(bl[0], bl[1], bl[2], bl[3], sb + 4u * (klw + k_l + kt * 8));
        #pragma unroll
        for (int mt = 0; mt < 2; mt++) {
            uint32_t ah[4], al[4];
            LDSM_X4(ah[0], ah[1], ah[2], ah[3], sb + 4u * (W_QH + q_l + mt * 1088 + kt * 8));
            LDSM_X4(al[0], al[1], al[2], al[3], sb + 4u * (W_QL + q_l + mt * 1088 + kt * 8));
            mma16816(sacc[mt][0], ah, bh);
            mma16816(sacc[mt][0], ah, bl);
            mma16816(sacc[mt][0], al, bh);
            mma16816(sacc[mt][1], ah, bh + 2);
            mma16816(sacc[mt][1], ah, bl + 2);
            mma16816(sacc[mt][1], al, bh + 2);
        }
    }
}

// softmax -> P hi only (Pl*Vh correction dropped; l uses fp32 p)
__device__ __forceinline__ void softmax_store(uint32_t* sm32, float sacc[2][2][4],
        int phw, int mrow0, int sk0, int lr, int lc, float* lpart) {
    #pragma unroll
    for (int mt = 0; mt < 2; mt++) {
        #pragma unroll
        for (int nt = 0; nt < 2; nt++) {
            float* c = sacc[mt][nt];
            float p0 = __expf(c[0] - SOFTMAX_SHIFT);
            float p1 = __expf(c[1] - SOFTMAX_SHIFT);
            float p2 = __expf(c[2] - SOFTMAX_SHIFT);
            float p3 = __expf(c[3] - SOFTMAX_SHIFT);
            lpart[mt * 2 + 0] += p0 + p1;
            lpart[mt * 2 + 1] += p2 + p3;
            int r0w = (mrow0 + mt * 16 + lr) * 20 + sk0 / 2 + nt * 4 + lc;
            int r1w = r0w + 160;
            sm32[phw + r0w] = pack_bf16x2(p0, p1);
            sm32[phw + r1w] = pack_bf16x2(p2, p3);
        }
    }
}

// O += Ph@(Vh+Vl): 2-term
__device__ __forceinline__ void compute_PV(uint32_t sb, int phw, int vhw, int vlw,
        int mrow0, int oc0, int lane, float (*oacc)[8][4]) {
    uint32_t p_l = (uint32_t)((mrow0 + (lane & 15)) * 20 + (lane >> 4) * 4);
    uint32_t v_l = (uint32_t)((((lane >> 4) << 3) + (lane & 7)) * 20 + ((lane >> 3) & 1) * 4);
    #pragma unroll
    for (int kt = 0; kt < 2; kt++) {
        uint32_t aph[2][4];
        LDSM_X4(aph[0][0], aph[0][1], aph[0][2], aph[0][3], sb + 4u * (phw + p_l + kt * 8));
        LDSM_X4(aph[1][0], aph[1][1], aph[1][2], aph[1][3], sb + 4u * (phw + p_l + 320 + kt * 8));
        #pragma unroll
        for (int ntp = 0; ntp < 4; ntp++) {
            uint32_t bvh[4], bvl[4];
            uint32_t vb = (uint32_t)((oc0 + ntp * 16) * 20) + v_l + kt * 8;
            LDSM_X4(bvh[0], bvh[1], bvh[2], bvh[3], sb + 4u * (vhw + vb));
            LDSM_X4(bvl[0], bvl[1], bvl[2], bvl[3], sb + 4u * (vlw + vb));
            #pragma unroll
            for (int mt = 0; mt < 2; mt++) {
                mma16816(oacc[mt][2 * ntp],     aph[mt], bvh);
                mma16816(oacc[mt][2 * ntp],     aph[mt], bvl);
                mma16816(oacc[mt][2 * ntp + 1], aph[mt], bvh + 2);
                mma16816(oacc[mt][2 * ntp + 1], aph[mt], bvl + 2);
            }
        }
    }
}

__global__ __launch_bounds__(256, 1) void attn_kernel(
    const float* __restrict__ Wo,
    const float* __restrict__ bo,
    float* __restrict__ outdst)
{
    extern __shared__ uint32_t sm32[];
    float* smf = (float*)sm32;
    uint32_t sb = smem_addr_u32(sm32);

    int tid = threadIdx.x, wid = tid >> 5, lane = tid & 31;
    int lr = lane >> 2, lc = lane & 3;
    int qt = blockIdx.x, bbx = blockIdx.y;
    size_t qrow0 = (size_t)bbx * SEQ + (size_t)qt * 128;
    size_t krow0 = (size_t)bbx * SEQ;
    size_t vch0  = (size_t)bbx * CDIM;

    int mrow0 = (wid >> 1) * 32;
    int sk0   = (wid & 1) * 16;
    int oc0   = (wid & 1) * 64;

    if (tid < 128) smf[W_LRED + tid] = 0.0f;

    // Q (hi+lo) via cp.async
    #pragma unroll
    for (int j = 0; j < 16; j++) {
        int id = tid + j * 256;
        int hi = id < 2048;
        int c = id & 2047;
        int row = c >> 4, ch8 = c & 15;
        uint32_t dst = sb + (uint32_t)(((hi ? W_QH : W_QL) + row * 68 + ch8 * 4) * 4);
        const __nv_bfloat16* src = (hi ? g_qh : g_ql) + (qrow0 + row) * CDIM + ch8 * 8;
        CP_ASYNC16(dst, src);
    }
    load_K_tile(sb, tid, W_KH0, W_KL0, krow0);
    load_V_tile(sb, tid, W_VH0, W_VH0 + 2560, vch0, 0);
    CP_COMMIT();
    load_K_tile(sb, tid, W_KH1, W_KL1, krow0 + 32);
    load_V_tile(sb, tid, W_VH0 + 5120, W_VH0 + 7680, vch0, 32);
    CP_COMMIT();

    float oacc[2][8][4];
    #pragma unroll
    for (int mt = 0; mt < 2; mt++)
        #pragma unroll
        for (int nt = 0; nt < 8; nt++)
            #pragma unroll
            for (int r = 0; r < 4; r++) oacc[mt][nt][r] = 0.0f;
    float lpart[4] = {0.0f, 0.0f, 0.0f, 0.0f};
    float sacc[2][2][4];

    // prologue: S(0) + P(0)
    CP_WAIT1();
    __syncthreads();
    compute_S(sb, W_KH0, W_KL0, mrow0, sk0, lane, sacc);
    softmax_store(sm32, sacc, W_PH0, mrow0, sk0, lr, lc, lpart);

    int vcur = 0;
    for (int t = 0; t < SEQ / 32; t++) {
        if (t < 127) CP_WAIT0();
        __syncthreads();

        if (t < 126) {
            int vpf = vcur - 1; if (vpf < 0) vpf += 3;
            load_K_tile(sb, tid, (t & 1) ? W_KH1 : W_KH0, (t & 1) ? W_KL1 : W_KL0,
                        krow0 + (size_t)(t + 2) * 32);
            load_V_tile(sb, tid, W_VH0 + vpf * 5120, W_VH0 + vpf * 5120 + 2560,
                        vch0, (t + 2) * 32);
            CP_COMMIT();
        }

        if (t < 127)
            compute_S(sb, ((t + 1) & 1) ? W_KH1 : W_KH0,
                      ((t + 1) & 1) ? W_KL1 : W_KL0, mrow0, sk0, lane, sacc);

        {
            int phw = W_PH0 + (t & 1) * 5120;
            int vhw = W_VH0 + vcur * 5120;
            compute_PV(sb, phw, vhw, vhw + 2560, mrow0, oc0, lane, oacc);
        }

        if (t < 127) {
            int phw = W_PH0 + ((t + 1) & 1) * 5120;
            softmax_store(sm32, sacc, phw, mrow0, sk0, lr, lc, lpart);
        }

        vcur = (vcur == 2) ? 0 : vcur + 1;
    }

    // ---- l reduction ----
    __syncthreads();
    #pragma unroll
    for (int i = 0; i < 4; i++) {
        int row = mrow0 + (i >> 1) * 16 + lr + 8 * (i & 1);
        atomicAdd(&smf[W_LRED + row], lpart[i]);
    }
    __syncthreads();
    float rl[4];
    #pragma unroll
    for (int i = 0; i < 4; i++) {
        int row = mrow0 + (i >> 1) * 16 + lr + 8 * (i & 1);
        rl[i] = 1.0f / smf[W_LRED + row];
    }
    __syncthreads();

    // ---- write normalized O; load Wo ----
    #pragma unroll
    for (int mt = 0; mt < 2; mt++)
        #pragma unroll
        for (int nt = 0; nt < 8; nt++) {
            int ch = oc0 + nt * 8 + 2 * lc;
            int ra = mrow0 + mt * 16 + lr;
            smf[W_OS + ra * 129 + ch]           = oacc[mt][nt][0] * rl[mt * 2];
            smf[W_OS + ra * 129 + ch + 1]       = oacc[mt][nt][1] * rl[mt * 2];
            smf[W_OS + (ra + 8) * 129 + ch]     = oacc[mt][nt][2] * rl[mt * 2 + 1];
            smf[W_OS + (ra + 8) * 129 + ch + 1] = oacc[mt][nt][3] * rl[mt * 2 + 1];
        }
    #pragma unroll
    for (int j = 0; j < 16; j++) {
        int idx = tid + j * 256;
        int rr = idx >> 5, cc = idx & 31;
        *(float4*)(smf + W_WS + rr * 128 + cc * 4) = *(const float4*)(Wo + (size_t)rr * 128 + cc * 4);
    }
    __syncthreads();

    // ---- out-proj ----
    {
        int row = tid >> 1, half = tid & 1;
        float facc[64];
        #pragma unroll
        for (int j = 0; j < 64; j++) facc[j] = 0.0f;
        #pragma unroll 4
        for (int k = 0; k < 128; k++) {
            float o = smf[W_OS + row * 129 + k];
            #pragma unroll
            for (int c4 = 0; c4 < 16; c4++) {
                float4 w = *(const float4*)(smf + W_WS + k * 128 + half * 64 + c4 * 4);
                facc[c4 * 4 + 0] += o * w.x;
                facc[c4 * 4 + 1] += o * w.y;
                facc[c4 * 4 + 2] += o * w.z;
                facc[c4 * 4 + 3] += o * w.w;
            }
        }
        #pragma unroll
        for (int c4 = 0; c4 < 16; c4++) {
            float4 bb = *(const float4*)(bo + half * 64 + c4 * 4);
            float4 f;
            f.x = facc[c4 * 4 + 0] + bb.x;
            f.y = facc[c4 * 4 + 1] + bb.y;
            f.z = facc[c4 * 4 + 2] + bb.z;
            f.w = facc[c4 * 4 + 3] + bb.w;
            *(float4*)(outdst + (qrow0 + row) * CDIM + half * 64 + c4 * 4) = f;
        }
    }
}

// ---------------- eager module load ----------------
namespace {
struct CudaPrewarm {
    CudaPrewarm() {
        cudaFuncAttributes a;
        cudaFuncGetAttributes(&a, (const void*)ln_qkv_kernel);
        cudaFuncGetAttributes(&a, (const void*)attn_kernel);
        cudaFuncSetAttribute(attn_kernel, cudaFuncAttributeMaxDynamicSharedMemorySize, SMEM_BYTES);
    }
};
CudaPrewarm g_prewarm;
}

// ---------------- launch ----------------
extern "C" void kernel_launch(void* const* d_in, const int* in_sizes, int n_in,
                              void* d_out, int out_size)
{
    const float* x     = (const float*)d_in[0];
    const float* gamma = (const float*)d_in[1];
    const float* beta  = (const float*)d_in[2];
    const float* Wq    = (const float*)d_in[3];
    const float* bq    = (const float*)d_in[4];
    const float* Wk    = (const float*)d_in[5];
    const float* bk    = (const float*)d_in[6];
    const float* Wv    = (const float*)d_in[7];
    const float* bv    = (const float*)d_in[8];
    const float* Wo    = (const float*)d_in[9];
    const float* bo    = (const float*)d_in[10];
    float* out = (float*)d_out;

    cudaFuncSetAttribute(attn_kernel, cudaFuncAttributeMaxDynamicSharedMemorySize, SMEM_BYTES);

    ln_qkv_kernel<<<NTOK / 64, 256>>>(x, gamma, beta, Wq, bq, Wk, bk, Wv, bv);
    attn_kernel<<<dim3(SEQ / 128, BATCH), 256, SMEM_BYTES>>>(Wo, bo, out);
}